// round 1
// baseline (speedup 1.0000x reference)
#include <cuda_runtime.h>
#include <cuda_fp16.h>
#include <math.h>
#include <stdint.h>

#define N_NODES 8192
#define NW 64

// ---------------- scratch (device globals; no runtime allocation) ----------------
__device__ __half g_E[(size_t)N_NODES * N_NODES];      // 128MB, unnormalized exp(exp(-a*d))
__device__ float  g_Z[N_NODES];                        // row sums of g_E
__device__ float  g_X1f[N_NODES * NW];
__device__ __half g_X1t[NW * N_NODES];                 // transposed [n][row] fp16
__device__ float  g_X2f[N_NODES * NW];
__device__ __half g_X2t[NW * N_NODES];
__device__ float  g_Y[N_NODES * NW];
__device__ float  g_Yp[4][N_NODES * NW];               // split-K partials
__device__ __align__(16) float2 g_ep[N_NODES];         // (eta, phi) packed
__device__ float  g_sp[256 * NW];                      // per-block column-sum partials

__device__ __forceinline__ float ex2f(float x) {
    float y;
    asm("ex2.approx.f32 %0, %1;" : "=f"(y) : "f"(x));
    return y;
}

// ---------------- K0: X1 = relu(x@W1+b1), pack (eta,phi) ----------------
__global__ void prep_kernel(const float* __restrict__ x, const float* __restrict__ W1,
                            const float* __restrict__ b1) {
    int row = blockIdx.x * 4 + (threadIdx.x >> 6);
    int n = threadIdx.x & 63;
    float acc = b1[n];
#pragma unroll
    for (int k = 0; k < 7; k++) acc += x[row * 7 + k] * W1[k * NW + n];
    acc = fmaxf(acc, 0.0f);
    g_X1f[row * NW + n] = acc;
    g_X1t[(size_t)n * N_NODES + row] = __float2half(acc);
    if (n == 0) {
        g_ep[row] = make_float2(x[row * 7 + 1], x[row * 7 + 2]);
    }
}

// ---------------- K1: E[i][j] = exp(exp(-alpha*dRdR)), Z[i] = rowsum ----------------
__global__ __launch_bounds__(256) void edges_kernel(const float* __restrict__ alpha_p) {
    int tid = threadIdx.x;
    int lane = tid & 31;
    int wid = tid >> 5;
    int r0 = blockIdx.x * 8;
    const float L2E = 1.4426950408889634f;
    float c1 = -alpha_p[0] * L2E;

    float ei[8], pii[8];
#pragma unroll
    for (int r = 0; r < 8; r++) {
        float2 v = g_ep[r0 + r];
        ei[r] = v.x; pii[r] = v.y;
    }
    float z[8];
#pragma unroll
    for (int r = 0; r < 8; r++) z[r] = 0.0f;

    const float TWO_PI = 6.283185307179586f;

    for (int it = 0; it < 8; it++) {
        int j = it * 1024 + tid * 4;
        float4 f0 = *reinterpret_cast<const float4*>(&g_ep[j]);
        float4 f1 = *reinterpret_cast<const float4*>(&g_ep[j + 2]);
        float ej[4] = {f0.x, f0.z, f1.x, f1.z};
        float pj[4] = {f0.y, f0.w, f1.y, f1.w};
#pragma unroll
        for (int r = 0; r < 8; r++) {
            float e4[4];
#pragma unroll
            for (int q = 0; q < 4; q++) {
                float de = ei[r] - ej[q];
                float dp = fabsf(pii[r] - pj[q]);
                dp = fminf(dp, TWO_PI - dp);            // == where(dp>pi, 2pi-dp, dp)
                float d = de * de + dp * dp;
                float a = ex2f(c1 * d);                  // exp(-alpha*d)
                float e = ex2f(a * L2E);                 // exp(a)
                e4[q] = e;
                z[r] += e;
            }
            __half2* eo = reinterpret_cast<__half2*>(g_E + (size_t)(r0 + r) * N_NODES + j);
            eo[0] = __floats2half2_rn(e4[0], e4[1]);
            eo[1] = __floats2half2_rn(e4[2], e4[3]);
        }
    }
    // reduce z across block
#pragma unroll
    for (int r = 0; r < 8; r++)
        for (int o = 16; o; o >>= 1) z[r] += __shfl_down_sync(0xffffffffu, z[r], o);
    __shared__ float sred[64];
    if (lane == 0) {
#pragma unroll
        for (int r = 0; r < 8; r++) sred[r * 8 + wid] = z[r];
    }
    __syncthreads();
    if (tid < 8) {
        float t = 0.0f;
#pragma unroll
        for (int w = 0; w < 8; w++) t += sred[tid * 8 + w];
        g_Z[r0 + tid] = t;
    }
}

// ---------------- K2/K4: Yp[kq] = E[rows, kslice] @ X  (mma.sync fp16) ----------------
__global__ __launch_bounds__(128) void gemm_kernel(int which) {
    const __half* __restrict__ Xt = which ? g_X2t : g_X1t;
    int lane = threadIdx.x & 31;
    int warp = threadIdx.x >> 5;
    int rtile = blockIdx.x >> 2;
    int kq = blockIdx.x & 3;
    int rbase = rtile * 64 + warp * 16;
    int kbeg = kq * 2048;
    int gr = lane >> 2;          // 0..7
    int qp = (lane & 3) << 1;    // 0,2,4,6

    const __half* a0p = g_E + (size_t)(rbase + gr) * N_NODES + qp;
    const __half* a1p = a0p + (size_t)8 * N_NODES;
    const __half* bp = Xt + (size_t)gr * N_NODES + qp;

    float acc[8][4];
#pragma unroll
    for (int t = 0; t < 8; t++)
#pragma unroll
        for (int q = 0; q < 4; q++) acc[t][q] = 0.0f;

#pragma unroll 2
    for (int k0 = kbeg; k0 < kbeg + 2048; k0 += 16) {
        uint32_t a0 = *reinterpret_cast<const uint32_t*>(a0p + k0);
        uint32_t a1 = *reinterpret_cast<const uint32_t*>(a1p + k0);
        uint32_t a2 = *reinterpret_cast<const uint32_t*>(a0p + k0 + 8);
        uint32_t a3 = *reinterpret_cast<const uint32_t*>(a1p + k0 + 8);
#pragma unroll
        for (int t = 0; t < 8; t++) {
            uint32_t b0 = *reinterpret_cast<const uint32_t*>(bp + (size_t)t * 8 * N_NODES + k0);
            uint32_t b1 = *reinterpret_cast<const uint32_t*>(bp + (size_t)t * 8 * N_NODES + k0 + 8);
            asm volatile(
                "mma.sync.aligned.m16n8k16.row.col.f32.f16.f16.f32 "
                "{%0,%1,%2,%3}, {%4,%5,%6,%7}, {%8,%9}, {%0,%1,%2,%3};"
                : "+f"(acc[t][0]), "+f"(acc[t][1]), "+f"(acc[t][2]), "+f"(acc[t][3])
                : "r"(a0), "r"(a1), "r"(a2), "r"(a3), "r"(b0), "r"(b1));
        }
    }

    int r0 = rbase + gr, r1 = r0 + 8;
    float* Yp = g_Yp[kq];
#pragma unroll
    for (int t = 0; t < 8; t++) {
        int c = t * 8 + qp;
        Yp[r0 * NW + c]     = acc[t][0];
        Yp[r0 * NW + c + 1] = acc[t][1];
        Yp[r1 * NW + c]     = acc[t][2];
        Yp[r1 * NW + c + 1] = acc[t][3];
    }
}

// ---------------- combine: Y = (sum_k Yp)/Z + X ----------------
__global__ void combine_kernel(int which) {
    const float* __restrict__ Xf = which ? g_X2f : g_X1f;
    int idx = blockIdx.x * 256 + threadIdx.x;
    int row = idx >> 6;
    float v = g_Yp[0][idx] + g_Yp[1][idx] + g_Yp[2][idx] + g_Yp[3][idx];
    g_Y[idx] = v / g_Z[row] + Xf[idx];
}

// ---------------- K3: V1 = relu(Y@wt1+bs1); X2 = relu(V1@W2+b2) ----------------
__global__ __launch_bounds__(256) void mid_kernel(const float* __restrict__ wt1,
                                                  const float* __restrict__ bs1,
                                                  const float* __restrict__ W2,
                                                  const float* __restrict__ b2) {
    __shared__ float s_w1[NW * NW];
    __shared__ float s_w2[NW * NW];
    __shared__ float s_y[32 * NW];
    int tid = threadIdx.x;
    int r0 = blockIdx.x * 32;
    for (int i = tid; i < NW * NW; i += 256) { s_w1[i] = wt1[i]; s_w2[i] = W2[i]; }
    for (int i = tid; i < 32 * NW; i += 256) s_y[i] = g_Y[r0 * NW + i];
    __syncthreads();

    int n = tid & 63, g = tid >> 6;
    float bsv = bs1[0];
    float vreg[8];
#pragma unroll
    for (int p = 0; p < 8; p++) {
        int rl = g + p * 4;
        float acc = bsv;
#pragma unroll
        for (int k = 0; k < NW; k++) acc += s_y[rl * NW + k] * s_w1[k * NW + n];
        vreg[p] = fmaxf(acc, 0.0f);
    }
    __syncthreads();
#pragma unroll
    for (int p = 0; p < 8; p++) s_y[(g + p * 4) * NW + n] = vreg[p];
    __syncthreads();

    float b2v = b2[n];
#pragma unroll
    for (int p = 0; p < 8; p++) {
        int rl = g + p * 4;
        float acc = b2v;
#pragma unroll
        for (int k = 0; k < NW; k++) acc += s_y[rl * NW + k] * s_w2[k * NW + n];
        acc = fmaxf(acc, 0.0f);
        int row = r0 + rl;
        g_X2f[row * NW + n] = acc;
        g_X2t[(size_t)n * N_NODES + row] = __float2half(acc);
    }
}

// ---------------- K5: V2 = relu(Y@wt2+bs2); per-block column partial sums ----------------
__global__ __launch_bounds__(256) void last_kernel(const float* __restrict__ wt2,
                                                   const float* __restrict__ bs2) {
    __shared__ float s_w[NW * NW];
    __shared__ float s_y[32 * NW];
    __shared__ float s_part[256];
    int tid = threadIdx.x;
    int r0 = blockIdx.x * 32;
    for (int i = tid; i < NW * NW; i += 256) s_w[i] = wt2[i];
    for (int i = tid; i < 32 * NW; i += 256) s_y[i] = g_Y[r0 * NW + i];
    __syncthreads();

    int n = tid & 63, g = tid >> 6;
    float bv = bs2[0];
    float tsum = 0.0f;
#pragma unroll
    for (int p = 0; p < 8; p++) {
        int rl = g + p * 4;
        float acc = bv;
#pragma unroll
        for (int k = 0; k < NW; k++) acc += s_y[rl * NW + k] * s_w[k * NW + n];
        tsum += fmaxf(acc, 0.0f);
    }
    s_part[tid] = tsum;
    __syncthreads();
    if (tid < 64)
        g_sp[blockIdx.x * NW + tid] =
            s_part[tid] + s_part[tid + 64] + s_part[tid + 128] + s_part[tid + 192];
}

// ---------------- K6: out = sigmoid(s@Wl + bl) ----------------
__global__ void final_kernel(const float* __restrict__ Wl, const float* __restrict__ bl,
                             float* __restrict__ out) {
    int n = threadIdx.x;  // 64 threads
    float s = 0.0f;
    for (int b = 0; b < 256; b++) s += g_sp[b * NW + n];
    float v = s * Wl[n];
    __shared__ float sh[64];
    sh[n] = v;
    __syncthreads();
    if (n < 32) {
        float t = sh[n] + sh[n + 32];
        for (int o = 16; o; o >>= 1) t += __shfl_down_sync(0xffffffffu, t, o);
        if (n == 0) out[0] = 1.0f / (1.0f + expf(-(t + bl[0])));
    }
}

// ---------------- launch ----------------
extern "C" void kernel_launch(void* const* d_in, const int* in_sizes, int n_in,
                              void* d_out, int out_size) {
    (void)in_sizes; (void)n_in; (void)out_size;
    const float* x     = (const float*)d_in[0];
    const float* alpha = (const float*)d_in[1];
    const float* W1    = (const float*)d_in[2];
    const float* b1    = (const float*)d_in[3];
    const float* wt1   = (const float*)d_in[4];
    const float* bs1   = (const float*)d_in[5];
    const float* W2    = (const float*)d_in[6];
    const float* b2    = (const float*)d_in[7];
    const float* wt2   = (const float*)d_in[8];
    const float* bs2   = (const float*)d_in[9];
    const float* Wl    = (const float*)d_in[10];
    const float* bl    = (const float*)d_in[11];
    float* out = (float*)d_out;

    prep_kernel<<<2048, 256>>>(x, W1, b1);
    edges_kernel<<<1024, 256>>>(alpha);

    gemm_kernel<<<512, 128>>>(0);
    combine_kernel<<<2048, 256>>>(0);
    mid_kernel<<<256, 256>>>(wt1, bs1, W2, b2);

    gemm_kernel<<<512, 128>>>(1);
    combine_kernel<<<2048, 256>>>(1);
    last_kernel<<<256, 256>>>(wt2, bs2);

    final_kernel<<<1, 64>>>(Wl, bl, out);
}

// round 2
// speedup vs baseline: 1.8037x; 1.8037x over previous
#include <cuda_runtime.h>
#include <cuda_fp16.h>
#include <math.h>
#include <stdint.h>

#define N_NODES 8192
#define NW 64
#define SPLITK 8
#define KSLICE (N_NODES / SPLITK)   // 1024
#define BM 128
#define BN 64
#define BK 64
#define NSTAGE (KSLICE / BK)        // 16

// ---------------- scratch (device globals; no runtime allocation) ----------------
__device__ __half g_E[(size_t)N_NODES * N_NODES];      // 128MB, unnormalized exp(exp(-a*d))
__device__ float  g_Z[N_NODES];                        // row sums of g_E
__device__ float  g_X1f[N_NODES * NW];
__device__ __half g_X1t[NW * N_NODES];                 // transposed [n][row] fp16
__device__ float  g_X2f[N_NODES * NW];
__device__ __half g_X2t[NW * N_NODES];
__device__ float  g_Y[N_NODES * NW];
__device__ float  g_Yp[SPLITK][N_NODES * NW];          // split-K partials
__device__ __align__(16) float2 g_ep[N_NODES];         // (eta, phi) packed
__device__ float  g_sp[256 * NW];                      // per-block column-sum partials

__device__ __forceinline__ float ex2f(float x) {
    float y;
    asm("ex2.approx.f32 %0, %1;" : "=f"(y) : "f"(x));
    return y;
}

// ---------------- K0: X1 = relu(x@W1+b1), pack (eta,phi) ----------------
__global__ void prep_kernel(const float* __restrict__ x, const float* __restrict__ W1,
                            const float* __restrict__ b1) {
    int row = blockIdx.x * 4 + (threadIdx.x >> 6);
    int n = threadIdx.x & 63;
    float acc = b1[n];
#pragma unroll
    for (int k = 0; k < 7; k++) acc += x[row * 7 + k] * W1[k * NW + n];
    acc = fmaxf(acc, 0.0f);
    g_X1f[row * NW + n] = acc;
    g_X1t[(size_t)n * N_NODES + row] = __float2half(acc);
    if (n == 0) {
        g_ep[row] = make_float2(x[row * 7 + 1], x[row * 7 + 2]);
    }
}

// ---------------- K1: E[i][j] = exp(exp(-alpha*dRdR)), Z[i] = rowsum ----------------
__global__ __launch_bounds__(256) void edges_kernel(const float* __restrict__ alpha_p) {
    int tid = threadIdx.x;
    int lane = tid & 31;
    int wid = tid >> 5;
    int r0 = blockIdx.x * 8;
    const float L2E = 1.4426950408889634f;
    float c1 = -alpha_p[0] * L2E;

    float ei[8], pii[8];
#pragma unroll
    for (int r = 0; r < 8; r++) {
        float2 v = g_ep[r0 + r];
        ei[r] = v.x; pii[r] = v.y;
    }
    float z[8];
#pragma unroll
    for (int r = 0; r < 8; r++) z[r] = 0.0f;

    const float TWO_PI = 6.283185307179586f;

    for (int it = 0; it < 8; it++) {
        int j = it * 1024 + tid * 4;
        float4 f0 = *reinterpret_cast<const float4*>(&g_ep[j]);
        float4 f1 = *reinterpret_cast<const float4*>(&g_ep[j + 2]);
        float ej[4] = {f0.x, f0.z, f1.x, f1.z};
        float pj[4] = {f0.y, f0.w, f1.y, f1.w};
#pragma unroll
        for (int r = 0; r < 8; r++) {
            float e4[4];
#pragma unroll
            for (int q = 0; q < 4; q++) {
                float de = ei[r] - ej[q];
                float dp = fabsf(pii[r] - pj[q]);
                dp = fminf(dp, TWO_PI - dp);
                float d = de * de + dp * dp;
                float a = ex2f(c1 * d);                  // exp(-alpha*d)
                float e = ex2f(a * L2E);                 // exp(a)
                e4[q] = e;
                z[r] += e;
            }
            __half2* eo = reinterpret_cast<__half2*>(g_E + (size_t)(r0 + r) * N_NODES + j);
            eo[0] = __floats2half2_rn(e4[0], e4[1]);
            eo[1] = __floats2half2_rn(e4[2], e4[3]);
        }
    }
#pragma unroll
    for (int r = 0; r < 8; r++)
        for (int o = 16; o; o >>= 1) z[r] += __shfl_down_sync(0xffffffffu, z[r], o);
    __shared__ float sred[64];
    if (lane == 0) {
#pragma unroll
        for (int r = 0; r < 8; r++) sred[r * 8 + wid] = z[r];
    }
    __syncthreads();
    if (tid < 8) {
        float t = 0.0f;
#pragma unroll
        for (int w = 0; w < 8; w++) t += sred[tid * 8 + w];
        g_Z[r0 + tid] = t;
    }
}

// ---------------- tiled GEMM: Yp[kq] = E[rows, kslice] @ Xt^T ----------------
// Block: 128m x 64n x (BK=64 per stage), 8 warps (4m x 2n), double-buffered cp.async.
#define SA_STRIDE 72   // halfs per row (64 + 8 pad) -> 144B, conflict-free ldmatrix
#define SA_BUF (BM * SA_STRIDE)   // 9216 halfs
#define SB_BUF (BN * SA_STRIDE)   // 4608 halfs
#define GEMM_SMEM ((2 * SA_BUF + 2 * SB_BUF) * 2)  // 55296 bytes

__device__ __forceinline__ void cpa16(uint32_t dst, const void* src) {
    asm volatile("cp.async.cg.shared.global [%0], [%1], 16;\n" :: "r"(dst), "l"(src));
}

__global__ __launch_bounds__(256) void gemm_kernel(int which) {
    extern __shared__ __half smem[];
    const __half* __restrict__ Xt = which ? g_X2t : g_X1t;

    int tid = threadIdx.x;
    int lane = tid & 31;
    int warp = tid >> 5;
    int warp_m = warp >> 1;   // 0..3
    int warp_n = warp & 1;    // 0..1

    int rtile = blockIdx.x >> 3;
    int kq = blockIdx.x & 7;
    int rbase = rtile * BM;
    int kbeg = kq * KSLICE;

    uint32_t sA_base = (uint32_t)__cvta_generic_to_shared(smem);
    uint32_t sB_base = sA_base + 2 * SA_BUF * 2;

    // load-chunk coords (stage-invariant)
    int a_row[4], a_col[4];
#pragma unroll
    for (int i = 0; i < 4; i++) {
        int c = tid + i * 256;
        a_row[i] = c >> 3;
        a_col[i] = c & 7;
    }
    int b_row[2], b_col[2];
#pragma unroll
    for (int i = 0; i < 2; i++) {
        int c = tid + i * 256;
        b_row[i] = c >> 3;
        b_col[i] = c & 7;
    }

    auto load_stage = [&](int s, int buf) {
        const __half* asrc = g_E + (size_t)rbase * N_NODES + kbeg + s * BK;
#pragma unroll
        for (int i = 0; i < 4; i++) {
            uint32_t dst = sA_base + (uint32_t)(buf * SA_BUF + a_row[i] * SA_STRIDE + a_col[i] * 8) * 2;
            cpa16(dst, asrc + (size_t)a_row[i] * N_NODES + a_col[i] * 8);
        }
        const __half* bsrc = Xt + kbeg + s * BK;
#pragma unroll
        for (int i = 0; i < 2; i++) {
            uint32_t dst = sB_base + (uint32_t)(buf * SB_BUF + b_row[i] * SA_STRIDE + b_col[i] * 8) * 2;
            cpa16(dst, bsrc + (size_t)b_row[i] * N_NODES + b_col[i] * 8);
        }
        asm volatile("cp.async.commit_group;\n" ::: "memory");
    };

    float acc[2][4][4];
#pragma unroll
    for (int mt = 0; mt < 2; mt++)
#pragma unroll
        for (int nt = 0; nt < 4; nt++)
#pragma unroll
            for (int q = 0; q < 4; q++) acc[mt][nt][q] = 0.0f;

    load_stage(0, 0);

    int buf = 0;
    for (int s = 0; s < NSTAGE; s++) {
        asm volatile("cp.async.wait_group 0;\n" ::: "memory");
        __syncthreads();
        if (s + 1 < NSTAGE) load_stage(s + 1, buf ^ 1);

        // compute from smem[buf]
#pragma unroll
        for (int kk = 0; kk < 4; kk++) {
            uint32_t a[2][4];
#pragma unroll
            for (int mt = 0; mt < 2; mt++) {
                int row = warp_m * 32 + mt * 16 + (lane & 15);
                int col = kk * 16 + ((lane >> 4) << 3);
                uint32_t addr = sA_base + (uint32_t)(buf * SA_BUF + row * SA_STRIDE + col) * 2;
                asm volatile(
                    "ldmatrix.sync.aligned.m8n8.x4.shared.b16 {%0,%1,%2,%3}, [%4];"
                    : "=r"(a[mt][0]), "=r"(a[mt][1]), "=r"(a[mt][2]), "=r"(a[mt][3])
                    : "r"(addr));
            }
            uint32_t b[4][2];
#pragma unroll
            for (int g = 0; g < 2; g++) {
                int q = lane >> 3;
                int nt = g * 2 + (q >> 1);
                int koff = (q & 1) << 3;
                int n = warp_n * 32 + nt * 8 + (lane & 7);
                uint32_t addr = sB_base + (uint32_t)(buf * SB_BUF + n * SA_STRIDE + kk * 16 + koff) * 2;
                uint32_t t0, t1, t2, t3;
                asm volatile(
                    "ldmatrix.sync.aligned.m8n8.x4.shared.b16 {%0,%1,%2,%3}, [%4];"
                    : "=r"(t0), "=r"(t1), "=r"(t2), "=r"(t3)
                    : "r"(addr));
                b[g * 2][0] = t0; b[g * 2][1] = t1;
                b[g * 2 + 1][0] = t2; b[g * 2 + 1][1] = t3;
            }
#pragma unroll
            for (int mt = 0; mt < 2; mt++)
#pragma unroll
                for (int nt = 0; nt < 4; nt++) {
                    asm volatile(
                        "mma.sync.aligned.m16n8k16.row.col.f32.f16.f16.f32 "
                        "{%0,%1,%2,%3}, {%4,%5,%6,%7}, {%8,%9}, {%0,%1,%2,%3};"
                        : "+f"(acc[mt][nt][0]), "+f"(acc[mt][nt][1]),
                          "+f"(acc[mt][nt][2]), "+f"(acc[mt][nt][3])
                        : "r"(a[mt][0]), "r"(a[mt][1]), "r"(a[mt][2]), "r"(a[mt][3]),
                          "r"(b[nt][0]), "r"(b[nt][1]));
                }
        }
        __syncthreads();
        buf ^= 1;
    }

    // epilogue
    float* Yp = g_Yp[kq];
#pragma unroll
    for (int mt = 0; mt < 2; mt++) {
        int row = rbase + warp_m * 32 + mt * 16 + (lane >> 2);
#pragma unroll
        for (int nt = 0; nt < 4; nt++) {
            int col = warp_n * 32 + nt * 8 + ((lane & 3) << 1);
            float2* o0 = reinterpret_cast<float2*>(Yp + row * NW + col);
            float2* o1 = reinterpret_cast<float2*>(Yp + (row + 8) * NW + col);
            *o0 = make_float2(acc[mt][nt][0], acc[mt][nt][1]);
            *o1 = make_float2(acc[mt][nt][2], acc[mt][nt][3]);
        }
    }
}

// ---------------- combine: Y = (sum_k Yp)/Z + X ----------------
__global__ void combine_kernel(int which) {
    const float* __restrict__ Xf = which ? g_X2f : g_X1f;
    int i4 = blockIdx.x * 256 + threadIdx.x;
    int idx = i4 * 4;
    int row = idx >> 6;
    float4 v = *reinterpret_cast<const float4*>(&g_Yp[0][idx]);
#pragma unroll
    for (int p = 1; p < SPLITK; p++) {
        float4 t = *reinterpret_cast<const float4*>(&g_Yp[p][idx]);
        v.x += t.x; v.y += t.y; v.z += t.z; v.w += t.w;
    }
    float zi = 1.0f / g_Z[row];
    float4 xv = *reinterpret_cast<const float4*>(&Xf[idx]);
    float4 o;
    o.x = v.x * zi + xv.x;
    o.y = v.y * zi + xv.y;
    o.z = v.z * zi + xv.z;
    o.w = v.w * zi + xv.w;
    *reinterpret_cast<float4*>(&g_Y[idx]) = o;
}

// ---------------- K3: V1 = relu(Y@wt1+bs1); X2 = relu(V1@W2+b2) ----------------
__global__ __launch_bounds__(256) void mid_kernel(const float* __restrict__ wt1,
                                                  const float* __restrict__ bs1,
                                                  const float* __restrict__ W2,
                                                  const float* __restrict__ b2) {
    __shared__ float s_w1[NW * NW];
    __shared__ float s_w2[NW * NW];
    __shared__ float s_y[32 * NW];
    int tid = threadIdx.x;
    int r0 = blockIdx.x * 32;
    for (int i = tid; i < NW * NW; i += 256) { s_w1[i] = wt1[i]; s_w2[i] = W2[i]; }
    for (int i = tid; i < 32 * NW; i += 256) s_y[i] = g_Y[r0 * NW + i];
    __syncthreads();

    int n = tid & 63, g = tid >> 6;
    float bsv = bs1[0];
    float vreg[8];
#pragma unroll
    for (int p = 0; p < 8; p++) {
        int rl = g + p * 4;
        float acc = bsv;
#pragma unroll
        for (int k = 0; k < NW; k++) acc += s_y[rl * NW + k] * s_w1[k * NW + n];
        vreg[p] = fmaxf(acc, 0.0f);
    }
    __syncthreads();
#pragma unroll
    for (int p = 0; p < 8; p++) s_y[(g + p * 4) * NW + n] = vreg[p];
    __syncthreads();

    float b2v = b2[n];
#pragma unroll
    for (int p = 0; p < 8; p++) {
        int rl = g + p * 4;
        float acc = b2v;
#pragma unroll
        for (int k = 0; k < NW; k++) acc += s_y[rl * NW + k] * s_w2[k * NW + n];
        acc = fmaxf(acc, 0.0f);
        int row = r0 + rl;
        g_X2f[row * NW + n] = acc;
        g_X2t[(size_t)n * N_NODES + row] = __float2half(acc);
    }
}

// ---------------- K5: V2 = relu(Y@wt2+bs2); per-block column partial sums ----------------
__global__ __launch_bounds__(256) void last_kernel(const float* __restrict__ wt2,
                                                   const float* __restrict__ bs2) {
    __shared__ float s_w[NW * NW];
    __shared__ float s_y[32 * NW];
    __shared__ float s_part[256];
    int tid = threadIdx.x;
    int r0 = blockIdx.x * 32;
    for (int i = tid; i < NW * NW; i += 256) s_w[i] = wt2[i];
    for (int i = tid; i < 32 * NW; i += 256) s_y[i] = g_Y[r0 * NW + i];
    __syncthreads();

    int n = tid & 63, g = tid >> 6;
    float bv = bs2[0];
    float tsum = 0.0f;
#pragma unroll
    for (int p = 0; p < 8; p++) {
        int rl = g + p * 4;
        float acc = bv;
#pragma unroll
        for (int k = 0; k < NW; k++) acc += s_y[rl * NW + k] * s_w[k * NW + n];
        tsum += fmaxf(acc, 0.0f);
    }
    s_part[tid] = tsum;
    __syncthreads();
    if (tid < 64)
        g_sp[blockIdx.x * NW + tid] =
            s_part[tid] + s_part[tid + 64] + s_part[tid + 128] + s_part[tid + 192];
}

// ---------------- K6: out = sigmoid(s@Wl + bl) ----------------
__global__ void final_kernel(const float* __restrict__ Wl, const float* __restrict__ bl,
                             float* __restrict__ out) {
    int n = threadIdx.x;  // 64 threads
    float s = 0.0f;
    for (int b = 0; b < 256; b++) s += g_sp[b * NW + n];
    float v = s * Wl[n];
    __shared__ float sh[64];
    sh[n] = v;
    __syncthreads();
    if (n < 32) {
        float t = sh[n] + sh[n + 32];
        for (int o = 16; o; o >>= 1) t += __shfl_down_sync(0xffffffffu, t, o);
        if (n == 0) out[0] = 1.0f / (1.0f + expf(-(t + bl[0])));
    }
}

// ---------------- launch ----------------
extern "C" void kernel_launch(void* const* d_in, const int* in_sizes, int n_in,
                              void* d_out, int out_size) {
    (void)in_sizes; (void)n_in; (void)out_size;
    const float* x     = (const float*)d_in[0];
    const float* alpha = (const float*)d_in[1];
    const float* W1    = (const float*)d_in[2];
    const float* b1    = (const float*)d_in[3];
    const float* wt1   = (const float*)d_in[4];
    const float* bs1   = (const float*)d_in[5];
    const float* W2    = (const float*)d_in[6];
    const float* b2    = (const float*)d_in[7];
    const float* wt2   = (const float*)d_in[8];
    const float* bs2   = (const float*)d_in[9];
    const float* Wl    = (const float*)d_in[10];
    const float* bl    = (const float*)d_in[11];
    float* out = (float*)d_out;

    cudaFuncSetAttribute(gemm_kernel, cudaFuncAttributeMaxDynamicSharedMemorySize, GEMM_SMEM);

    prep_kernel<<<2048, 256>>>(x, W1, b1);
    edges_kernel<<<1024, 256>>>(alpha);

    gemm_kernel<<<512, 256, GEMM_SMEM>>>(0);
    combine_kernel<<<512, 256>>>(0);
    mid_kernel<<<256, 256>>>(wt1, bs1, W2, b2);

    gemm_kernel<<<512, 256, GEMM_SMEM>>>(1);
    combine_kernel<<<512, 256>>>(1);
    last_kernel<<<256, 256>>>(wt2, bs2);

    final_kernel<<<1, 64>>>(Wl, bl, out);
}

// round 3
// speedup vs baseline: 2.4919x; 1.3816x over previous
#include <cuda_runtime.h>
#include <cuda_fp16.h>
#include <math.h>
#include <stdint.h>

#define N_NODES 8192
#define NW 64
#define SPLITK 8
#define KSLICE (N_NODES / SPLITK)   // 1024
#define BM 128
#define BN 64
#define BK 64
#define NSTAGE (KSLICE / BK)        // 16

// ---------------- scratch (device globals; no runtime allocation) ----------------
__device__ float  g_Zp[SPLITK][N_NODES];               // split-K row-sum partials
__device__ float  g_X1f[N_NODES * NW];
__device__ __half g_X1t[NW * N_NODES];                 // transposed [n][row] fp16
__device__ float  g_X2f[N_NODES * NW];
__device__ __half g_X2t[NW * N_NODES];
__device__ float  g_Y[N_NODES * NW];
__device__ float  g_Yp[SPLITK][N_NODES * NW];          // split-K GEMM partials
__device__ __align__(16) float2 g_ep[N_NODES];         // (eta, phi) packed
__device__ float  g_sp[256 * NW];                      // per-block column-sum partials

__device__ __forceinline__ float ex2f(float x) {
    float y;
    asm("ex2.approx.f32 %0, %1;" : "=f"(y) : "f"(x));
    return y;
}

// ---------------- K0: X1 = relu(x@W1+b1), pack (eta,phi) ----------------
__global__ void prep_kernel(const float* __restrict__ x, const float* __restrict__ W1,
                            const float* __restrict__ b1) {
    int row = blockIdx.x * 4 + (threadIdx.x >> 6);
    int n = threadIdx.x & 63;
    float acc = b1[n];
#pragma unroll
    for (int k = 0; k < 7; k++) acc += x[row * 7 + k] * W1[k * NW + n];
    acc = fmaxf(acc, 0.0f);
    g_X1f[row * NW + n] = acc;
    g_X1t[(size_t)n * N_NODES + row] = __float2half(acc);
    if (n == 0) {
        g_ep[row] = make_float2(x[row * 7 + 1], x[row * 7 + 2]);
    }
}

// ---------------- fused GEMM: Yp[kq] = softmax-numerator(E)[rows, kslice] @ Xt^T ----
// E computed on the fly; Z partials accumulated. Block: 128m x 64n x 64k/stage,
// 8 warps (4m x 2n), double-buffered E smem + cp.async B.
#define SA_STRIDE 72   // halfs per row (64 + 8 pad) -> 144B, conflict-free ldmatrix
#define SA_BUF (BM * SA_STRIDE)   // 9216 halfs
#define SB_BUF (BN * SA_STRIDE)   // 4608 halfs
#define GEMM_SMEM ((2 * SA_BUF + 2 * SB_BUF) * 2)  // 55296 bytes

__device__ __forceinline__ void cpa16(uint32_t dst, const void* src) {
    asm volatile("cp.async.cg.shared.global [%0], [%1], 16;\n" :: "r"(dst), "l"(src));
}

__global__ __launch_bounds__(256) void fused_gemm_kernel(int which,
                                                         const float* __restrict__ alpha_p) {
    extern __shared__ __half smem[];
    const __half* __restrict__ Xt = which ? g_X2t : g_X1t;

    int tid = threadIdx.x;
    int lane = tid & 31;
    int warp = tid >> 5;
    int warp_m = warp >> 1;   // 0..3
    int warp_n = warp & 1;    // 0..1

    int rtile = blockIdx.x >> 3;
    int kq = blockIdx.x & 7;
    int rbase = rtile * BM;
    int kbeg = kq * KSLICE;

    uint32_t sA_base = (uint32_t)__cvta_generic_to_shared(smem);
    uint32_t sB_base = sA_base + 2 * SA_BUF * 2;

    const float L2E = 1.4426950408889634f;
    const float TWO_PI = 6.283185307179586f;
    float c1 = -alpha_p[0] * L2E;

    // ---- E-compute mapping: thread -> 8 rows x 4 cols of the 128x64 tile ----
    int ig = tid >> 4;          // 0..15 -> rows ig*8..ig*8+7
    int cg = tid & 15;          // 0..15 -> cols cg*4..cg*4+3
    float ei[8], pii[8];
#pragma unroll
    for (int r = 0; r < 8; r++) {
        float2 v = g_ep[rbase + ig * 8 + r];
        ei[r] = v.x; pii[r] = v.y;
    }
    float z[8];
#pragma unroll
    for (int r = 0; r < 8; r++) z[r] = 0.0f;

    // compute E tile for stage s into E-buffer b
    auto compute_E = [&](int s, int b) {
        int jbase = kbeg + s * BK + cg * 4;
        float4 f0 = *reinterpret_cast<const float4*>(&g_ep[jbase]);
        float4 f1 = *reinterpret_cast<const float4*>(&g_ep[jbase + 2]);
        float ej[4] = {f0.x, f0.z, f1.x, f1.z};
        float pj[4] = {f0.y, f0.w, f1.y, f1.w};
#pragma unroll
        for (int r = 0; r < 8; r++) {
            float e4[4];
#pragma unroll
            for (int q = 0; q < 4; q++) {
                float de = ei[r] - ej[q];
                float dp = fabsf(pii[r] - pj[q]);
                dp = fminf(dp, TWO_PI - dp);
                float d = de * de + dp * dp;
                float a = ex2f(c1 * d);                  // exp(-alpha*d)
                float e = ex2f(a * L2E);                 // exp(a)
                e4[q] = e;
                z[r] += e;
            }
            __half2* eo = reinterpret_cast<__half2*>(
                smem + b * SA_BUF + (ig * 8 + r) * SA_STRIDE + cg * 4);
            eo[0] = __floats2half2_rn(e4[0], e4[1]);
            eo[1] = __floats2half2_rn(e4[2], e4[3]);
        }
    };

    // ---- B load coords ----
    int b_row[2], b_col[2];
#pragma unroll
    for (int i = 0; i < 2; i++) {
        int c = tid + i * 256;
        b_row[i] = c >> 3;
        b_col[i] = c & 7;
    }
    auto load_B = [&](int s, int b) {
        const __half* bsrc = Xt + kbeg + s * BK;
#pragma unroll
        for (int i = 0; i < 2; i++) {
            uint32_t dst = sB_base + (uint32_t)(b * SB_BUF + b_row[i] * SA_STRIDE + b_col[i] * 8) * 2;
            cpa16(dst, bsrc + (size_t)b_row[i] * N_NODES + b_col[i] * 8);
        }
        asm volatile("cp.async.commit_group;\n" ::: "memory");
    };

    float acc[2][4][4];
#pragma unroll
    for (int mt = 0; mt < 2; mt++)
#pragma unroll
        for (int nt = 0; nt < 4; nt++)
#pragma unroll
            for (int q = 0; q < 4; q++) acc[mt][nt][q] = 0.0f;

    load_B(0, 0);
    compute_E(0, 0);

    int buf = 0;
    for (int s = 0; s < NSTAGE; s++) {
        if (s + 1 < NSTAGE) {
            load_B(s + 1, buf ^ 1);
            asm volatile("cp.async.wait_group 1;\n" ::: "memory");
        } else {
            asm volatile("cp.async.wait_group 0;\n" ::: "memory");
        }
        __syncthreads();   // E(s) stores + B(s) visible to all warps

        // ---- MMA on stage s ----
#pragma unroll
        for (int kk = 0; kk < 4; kk++) {
            uint32_t a[2][4];
#pragma unroll
            for (int mt = 0; mt < 2; mt++) {
                int row = warp_m * 32 + mt * 16 + (lane & 15);
                int col = kk * 16 + ((lane >> 4) << 3);
                uint32_t addr = sA_base + (uint32_t)(buf * SA_BUF + row * SA_STRIDE + col) * 2;
                asm volatile(
                    "ldmatrix.sync.aligned.m8n8.x4.shared.b16 {%0,%1,%2,%3}, [%4];"
                    : "=r"(a[mt][0]), "=r"(a[mt][1]), "=r"(a[mt][2]), "=r"(a[mt][3])
                    : "r"(addr));
            }
            uint32_t b[4][2];
#pragma unroll
            for (int g = 0; g < 2; g++) {
                int q = lane >> 3;
                int nt = g * 2 + (q >> 1);
                int koff = (q & 1) << 3;
                int n = warp_n * 32 + nt * 8 + (lane & 7);
                uint32_t addr = sB_base + (uint32_t)(buf * SB_BUF + n * SA_STRIDE + kk * 16 + koff) * 2;
                uint32_t t0, t1, t2, t3;
                asm volatile(
                    "ldmatrix.sync.aligned.m8n8.x4.shared.b16 {%0,%1,%2,%3}, [%4];"
                    : "=r"(t0), "=r"(t1), "=r"(t2), "=r"(t3)
                    : "r"(addr));
                b[g * 2][0] = t0; b[g * 2][1] = t1;
                b[g * 2 + 1][0] = t2; b[g * 2 + 1][1] = t3;
            }
#pragma unroll
            for (int mt = 0; mt < 2; mt++)
#pragma unroll
                for (int nt = 0; nt < 4; nt++) {
                    asm volatile(
                        "mma.sync.aligned.m16n8k16.row.col.f32.f16.f16.f32 "
                        "{%0,%1,%2,%3}, {%4,%5,%6,%7}, {%8,%9}, {%0,%1,%2,%3};"
                        : "+f"(acc[mt][nt][0]), "+f"(acc[mt][nt][1]),
                          "+f"(acc[mt][nt][2]), "+f"(acc[mt][nt][3])
                        : "r"(a[mt][0]), "r"(a[mt][1]), "r"(a[mt][2]), "r"(a[mt][3]),
                          "r"(b[nt][0]), "r"(b[nt][1]));
                }
        }

        // ---- compute E for stage s+1 into the other buffer (overlaps MMA pipes) ----
        if (s + 1 < NSTAGE) compute_E(s + 1, buf ^ 1);

        __syncthreads();
        buf ^= 1;
    }

    // ---- Z partial reduce: threads ig*16..ig*16+15 hold partial sums for same rows ----
#pragma unroll
    for (int r = 0; r < 8; r++) {
        float t = z[r];
#pragma unroll
        for (int o = 8; o; o >>= 1) t += __shfl_xor_sync(0xffffffffu, t, o);
        if ((lane & 15) == 0) g_Zp[kq][rbase + ig * 8 + r] = t;
    }

    // ---- epilogue: write Yp ----
    float* Yp = g_Yp[kq];
#pragma unroll
    for (int mt = 0; mt < 2; mt++) {
        int row = rbase + warp_m * 32 + mt * 16 + (lane >> 2);
#pragma unroll
        for (int nt = 0; nt < 4; nt++) {
            int col = warp_n * 32 + nt * 8 + ((lane & 3) << 1);
            float2* o0 = reinterpret_cast<float2*>(Yp + row * NW + col);
            float2* o1 = reinterpret_cast<float2*>(Yp + (row + 8) * NW + col);
            *o0 = make_float2(acc[mt][nt][0], acc[mt][nt][1]);
            *o1 = make_float2(acc[mt][nt][2], acc[mt][nt][3]);
        }
    }
}

// ---------------- combine: Y = (sum_k Yp)/(sum_k Zp) + X ----------------
__global__ void combine_kernel(int which) {
    const float* __restrict__ Xf = which ? g_X2f : g_X1f;
    int i4 = blockIdx.x * 256 + threadIdx.x;
    int idx = i4 * 4;
    int row = idx >> 6;
    float4 v = *reinterpret_cast<const float4*>(&g_Yp[0][idx]);
    float zs = g_Zp[0][row];
#pragma unroll
    for (int p = 1; p < SPLITK; p++) {
        float4 t = *reinterpret_cast<const float4*>(&g_Yp[p][idx]);
        v.x += t.x; v.y += t.y; v.z += t.z; v.w += t.w;
        zs += g_Zp[p][row];
    }
    float zi = 1.0f / zs;
    float4 xv = *reinterpret_cast<const float4*>(&Xf[idx]);
    float4 o;
    o.x = v.x * zi + xv.x;
    o.y = v.y * zi + xv.y;
    o.z = v.z * zi + xv.z;
    o.w = v.w * zi + xv.w;
    *reinterpret_cast<float4*>(&g_Y[idx]) = o;
}

// ---------------- K3: V1 = relu(Y@wt1+bs1); X2 = relu(V1@W2+b2) ----------------
__global__ __launch_bounds__(256) void mid_kernel(const float* __restrict__ wt1,
                                                  const float* __restrict__ bs1,
                                                  const float* __restrict__ W2,
                                                  const float* __restrict__ b2) {
    __shared__ float s_w1[NW * NW];
    __shared__ float s_w2[NW * NW];
    __shared__ float s_y[32 * NW];
    int tid = threadIdx.x;
    int r0 = blockIdx.x * 32;
    for (int i = tid; i < NW * NW; i += 256) { s_w1[i] = wt1[i]; s_w2[i] = W2[i]; }
    for (int i = tid; i < 32 * NW; i += 256) s_y[i] = g_Y[r0 * NW + i];
    __syncthreads();

    int n = tid & 63, g = tid >> 6;
    float bsv = bs1[0];
    float vreg[8];
#pragma unroll
    for (int p = 0; p < 8; p++) {
        int rl = g + p * 4;
        float acc = bsv;
#pragma unroll
        for (int k = 0; k < NW; k++) acc += s_y[rl * NW + k] * s_w1[k * NW + n];
        vreg[p] = fmaxf(acc, 0.0f);
    }
    __syncthreads();
#pragma unroll
    for (int p = 0; p < 8; p++) s_y[(g + p * 4) * NW + n] = vreg[p];
    __syncthreads();

    float b2v = b2[n];
#pragma unroll
    for (int p = 0; p < 8; p++) {
        int rl = g + p * 4;
        float acc = b2v;
#pragma unroll
        for (int k = 0; k < NW; k++) acc += s_y[rl * NW + k] * s_w2[k * NW + n];
        acc = fmaxf(acc, 0.0f);
        int row = r0 + rl;
        g_X2f[row * NW + n] = acc;
        g_X2t[(size_t)n * N_NODES + row] = __float2half(acc);
    }
}

// ---------------- K5: V2 = relu(Y@wt2+bs2); per-block column partial sums ----------------
__global__ __launch_bounds__(256) void last_kernel(const float* __restrict__ wt2,
                                                   const float* __restrict__ bs2) {
    __shared__ float s_w[NW * NW];
    __shared__ float s_y[32 * NW];
    __shared__ float s_part[256];
    int tid = threadIdx.x;
    int r0 = blockIdx.x * 32;
    for (int i = tid; i < NW * NW; i += 256) s_w[i] = wt2[i];
    for (int i = tid; i < 32 * NW; i += 256) s_y[i] = g_Y[r0 * NW + i];
    __syncthreads();

    int n = tid & 63, g = tid >> 6;
    float bv = bs2[0];
    float tsum = 0.0f;
#pragma unroll
    for (int p = 0; p < 8; p++) {
        int rl = g + p * 4;
        float acc = bv;
#pragma unroll
        for (int k = 0; k < NW; k++) acc += s_y[rl * NW + k] * s_w[k * NW + n];
        tsum += fmaxf(acc, 0.0f);
    }
    s_part[tid] = tsum;
    __syncthreads();
    if (tid < 64)
        g_sp[blockIdx.x * NW + tid] =
            s_part[tid] + s_part[tid + 64] + s_part[tid + 128] + s_part[tid + 192];
}

// ---------------- K6: out = sigmoid(s@Wl + bl) ----------------
__global__ void final_kernel(const float* __restrict__ Wl, const float* __restrict__ bl,
                             float* __restrict__ out) {
    int n = threadIdx.x;  // 64 threads
    float s = 0.0f;
    for (int b = 0; b < 256; b++) s += g_sp[b * NW + n];
    float v = s * Wl[n];
    __shared__ float sh[64];
    sh[n] = v;
    __syncthreads();
    if (n < 32) {
        float t = sh[n] + sh[n + 32];
        for (int o = 16; o; o >>= 1) t += __shfl_down_sync(0xffffffffu, t, o);
        if (n == 0) out[0] = 1.0f / (1.0f + expf(-(t + bl[0])));
    }
}

// ---------------- launch ----------------
extern "C" void kernel_launch(void* const* d_in, const int* in_sizes, int n_in,
                              void* d_out, int out_size) {
    (void)in_sizes; (void)n_in; (void)out_size;
    const float* x     = (const float*)d_in[0];
    const float* alpha = (const float*)d_in[1];
    const float* W1    = (const float*)d_in[2];
    const float* b1    = (const float*)d_in[3];
    const float* wt1   = (const float*)d_in[4];
    const float* bs1   = (const float*)d_in[5];
    const float* W2    = (const float*)d_in[6];
    const float* b2    = (const float*)d_in[7];
    const float* wt2   = (const float*)d_in[8];
    const float* bs2   = (const float*)d_in[9];
    const float* Wl    = (const float*)d_in[10];
    const float* bl    = (const float*)d_in[11];
    float* out = (float*)d_out;

    cudaFuncSetAttribute(fused_gemm_kernel, cudaFuncAttributeMaxDynamicSharedMemorySize, GEMM_SMEM);

    prep_kernel<<<2048, 256>>>(x, W1, b1);

    fused_gemm_kernel<<<512, 256, GEMM_SMEM>>>(0, alpha);
    combine_kernel<<<512, 256>>>(0);
    mid_kernel<<<256, 256>>>(wt1, bs1, W2, b2);

    fused_gemm_kernel<<<512, 256, GEMM_SMEM>>>(1, alpha);
    combine_kernel<<<512, 256>>>(1);
    last_kernel<<<256, 256>>>(wt2, bs2);

    final_kernel<<<1, 64>>>(Wl, bl, out);
}

// round 6
// speedup vs baseline: 2.8868x; 1.1585x over previous
#include <cuda_runtime.h>
#include <cuda_fp16.h>
#include <math.h>
#include <stdint.h>

#define N_NODES 8192
#define NW 64
#define SPLITK 16
#define KSLICE (N_NODES / SPLITK)   // 512
#define BM 128
#define NSTEP (KSLICE / 16)         // 32 k16-steps
#define BSTRIDE 520                 // halfs per B smem row (512 + 8 pad -> bank shift 4/row)
#define BSMEM (64 * BSTRIDE * 2)    // 66560 bytes

// ---------------- scratch (device globals) ----------------
__device__ float  g_Zp[SPLITK][N_NODES];
__device__ float  g_X1f[N_NODES * NW];
__device__ __half g_X1t[NW * N_NODES];
__device__ float  g_X2f[N_NODES * NW];
__device__ __half g_X2t[NW * N_NODES];
__device__ float  g_Yp[SPLITK][N_NODES * NW];
__device__ __align__(16) float2 g_ep[N_NODES];
__device__ float  g_sp[128 * NW];

__device__ __forceinline__ float ex2f(float x) {
    float y; asm("ex2.approx.f32 %0, %1;" : "=f"(y) : "f"(x)); return y;
}
__device__ __forceinline__ void cpa16(uint32_t dst, const void* src) {
    asm volatile("cp.async.cg.shared.global [%0], [%1], 16;\n" :: "r"(dst), "l"(src));
}
__device__ __forceinline__ uint32_t smem_u32(const void* p) {
    uint32_t a;
    asm("{ .reg .u64 t; cvta.to.shared.u64 t, %1; cvt.u32.u64 %0, t; }" : "=r"(a) : "l"(p));
    return a;
}

// ---------------- K0: X1 = relu(x@W1+b1), pack (eta,phi) ----------------
__global__ void prep_kernel(const float* __restrict__ x, const float* __restrict__ W1,
                            const float* __restrict__ b1) {
    int row = blockIdx.x * 4 + (threadIdx.x >> 6);
    int n = threadIdx.x & 63;
    float acc = b1[n];
#pragma unroll
    for (int k = 0; k < 7; k++) acc += x[row * 7 + k] * W1[k * NW + n];
    acc = fmaxf(acc, 0.0f);
    g_X1f[row * NW + n] = acc;
    g_X1t[(size_t)n * N_NODES + row] = __float2half(acc);
    if (n == 0) g_ep[row] = make_float2(x[row * 7 + 1], x[row * 7 + 2]);
}

// ---------------- fused GEMM: E computed in A-fragment registers ----------------
// grid: 64 rtiles x 16 kq. Block 256 = 8 warps, each warp owns 16 rows.
__global__ __launch_bounds__(256) void fused_gemm_kernel(int which,
                                                         const float* __restrict__ alpha_p) {
    extern __shared__ __half sB[];
    const __half* __restrict__ Xt = which ? g_X2t : g_X1t;

    int tid = threadIdx.x, lane = tid & 31, warp = tid >> 5;
    int rtile = blockIdx.x >> 4, kq = blockIdx.x & 15;
    int rbase = rtile * BM, kbeg = kq * KSLICE;

    // ---- stage B slice [64 n][512 k] into padded smem ----
    uint32_t sb_base = smem_u32(sB);
    {
#pragma unroll
        for (int it = 0; it < 16; it++) {
            int ch = tid + it * 256;        // 4096 chunks of 16B
            int n = ch >> 6, kc = ch & 63;
            uint32_t dst = sb_base + (uint32_t)(n * BSTRIDE + kc * 8) * 2;
            cpa16(dst, Xt + (size_t)n * N_NODES + kbeg + kc * 8);
        }
        asm volatile("cp.async.commit_group;\n" ::: "memory");
        asm volatile("cp.async.wait_group 0;\n" ::: "memory");
        __syncthreads();
    }

    const float L2E = 1.4426950408889634f;
    float sc = sqrtf(alpha_p[0] * L2E);
    const float C = 0.5287663729448977f;    // log2(log2 e)
    float wrapc = sc * 6.283185307179586f;  // scaled 2*pi

    // this thread's two rows
    int r = lane >> 2;
    int row0 = rbase + warp * 16 + r;
    float2 v0 = g_ep[row0];
    float2 v1 = g_ep[row0 + 8];
    float er0 = sc * v0.x, pr0 = sc * v0.y;
    float er1 = sc * v1.x, pr1 = sc * v1.y;
    float z0 = 0.f, z1 = 0.f;

    int c0 = (lane & 3) * 2;

    float acc[8][4];
#pragma unroll
    for (int nt = 0; nt < 8; nt++)
#pragma unroll
        for (int q = 0; q < 4; q++) acc[nt][q] = 0.0f;

    const __half* bwp = sB + (size_t)(lane >> 2) * BSTRIDE;  // n base = lane>>2 (+ nt*8 rows)

#pragma unroll 2
    for (int st = 0; st < NSTEP; st++) {
        int kb = kbeg + st * 16;
        // column coords (4 cols: c0, c0+1, c0+8, c0+9)
        float4 f0 = *reinterpret_cast<const float4*>(&g_ep[kb + c0]);
        float4 f1 = *reinterpret_cast<const float4*>(&g_ep[kb + c0 + 8]);
        float ej[4] = {sc * f0.x, sc * f0.z, sc * f1.x, sc * f1.z};
        float pj[4] = {sc * f0.y, sc * f0.w, sc * f1.y, sc * f1.w};

        float e0[4], e1[4];
#pragma unroll
        for (int q = 0; q < 4; q++) {
            float de = er0 - ej[q];
            float dp = fabsf(pr0 - pj[q]);
            dp = fminf(dp, wrapc - dp);
            float a = ex2f(fmaf(dp, -dp, fmaf(de, -de, C)));
            float e = ex2f(a);
            e0[q] = e; z0 += e;

            float de1 = er1 - ej[q];
            float dp1 = fabsf(pr1 - pj[q]);
            dp1 = fminf(dp1, wrapc - dp1);
            float a1 = ex2f(fmaf(dp1, -dp1, fmaf(de1, -de1, C)));
            float e1v = ex2f(a1);
            e1[q] = e1v; z1 += e1v;
        }
        __half2 A0 = __floats2half2_rn(e0[0], e0[1]);
        __half2 A1 = __floats2half2_rn(e1[0], e1[1]);
        __half2 A2 = __floats2half2_rn(e0[2], e0[3]);
        __half2 A3 = __floats2half2_rn(e1[2], e1[3]);
        uint32_t a0 = *reinterpret_cast<uint32_t*>(&A0);
        uint32_t a1 = *reinterpret_cast<uint32_t*>(&A1);
        uint32_t a2 = *reinterpret_cast<uint32_t*>(&A2);
        uint32_t a3 = *reinterpret_cast<uint32_t*>(&A3);

        int kl = st * 16 + c0;
#pragma unroll
        for (int nt = 0; nt < 8; nt++) {
            const __half* bp = bwp + (size_t)nt * 8 * BSTRIDE + kl;
            uint32_t b0 = *reinterpret_cast<const uint32_t*>(bp);
            uint32_t b1 = *reinterpret_cast<const uint32_t*>(bp + 8);
            asm volatile(
                "mma.sync.aligned.m16n8k16.row.col.f32.f16.f16.f32 "
                "{%0,%1,%2,%3}, {%4,%5,%6,%7}, {%8,%9}, {%0,%1,%2,%3};"
                : "+f"(acc[nt][0]), "+f"(acc[nt][1]), "+f"(acc[nt][2]), "+f"(acc[nt][3])
                : "r"(a0), "r"(a1), "r"(a2), "r"(a3), "r"(b0), "r"(b1));
        }
    }

    // ---- Z partials: sum over the 4 lanes sharing a row-group ----
    z0 += __shfl_xor_sync(0xffffffffu, z0, 1);
    z0 += __shfl_xor_sync(0xffffffffu, z0, 2);
    z1 += __shfl_xor_sync(0xffffffffu, z1, 1);
    z1 += __shfl_xor_sync(0xffffffffu, z1, 2);
    if ((lane & 3) == 0) {
        g_Zp[kq][row0] = z0;
        g_Zp[kq][row0 + 8] = z1;
    }

    // ---- epilogue ----
    float* Yp = g_Yp[kq];
#pragma unroll
    for (int nt = 0; nt < 8; nt++) {
        int col = nt * 8 + c0;
        *reinterpret_cast<float2*>(Yp + (size_t)row0 * NW + col) =
            make_float2(acc[nt][0], acc[nt][1]);
        *reinterpret_cast<float2*>(Yp + (size_t)(row0 + 8) * NW + col) =
            make_float2(acc[nt][2], acc[nt][3]);
    }
}

// ---------------- mid: combine + V1=relu(Y@wt1+bs1) + X2=relu(V1@W2+b2) ----------------
#define MID_SMEM ((4096 * 3 + 64) * 4)
__global__ __launch_bounds__(256) void mid_kernel(const float* __restrict__ wt1,
                                                  const float* __restrict__ bs1,
                                                  const float* __restrict__ W2,
                                                  const float* __restrict__ b2) {
    extern __shared__ float sm[];
    float* s_w1 = sm;
    float* s_w2 = sm + 4096;
    float* s_y  = sm + 8192;
    float* s_zi = sm + 12288;
    int tid = threadIdx.x;
    int r0 = blockIdx.x * 64;

    for (int i = tid; i < 4096; i += 256) { s_w1[i] = wt1[i]; s_w2[i] = W2[i]; }
    if (tid < 64) {
        float zs = 0.f;
#pragma unroll
        for (int p = 0; p < SPLITK; p++) zs += g_Zp[p][r0 + tid];
        s_zi[tid] = 1.0f / zs;
    }
    __syncthreads();

    const float4* X4 = reinterpret_cast<const float4*>(g_X1f + (size_t)r0 * NW);
    for (int i = tid; i < 1024; i += 256) {
        float4 v = reinterpret_cast<const float4*>(g_Yp[0] + (size_t)r0 * NW)[i];
#pragma unroll
        for (int p = 1; p < SPLITK; p++) {
            float4 t = reinterpret_cast<const float4*>(g_Yp[p] + (size_t)r0 * NW)[i];
            v.x += t.x; v.y += t.y; v.z += t.z; v.w += t.w;
        }
        float zi = s_zi[i >> 4];
        float4 xv = X4[i];
        reinterpret_cast<float4*>(s_y)[i] =
            make_float4(fmaf(v.x, zi, xv.x), fmaf(v.y, zi, xv.y),
                        fmaf(v.z, zi, xv.z), fmaf(v.w, zi, xv.w));
    }
    __syncthreads();

    int cgp = tid & 15, rg = tid >> 4;
    int c0 = cgp * 4, rl0 = rg * 4;
    float bsv = bs1[0];
    float acc[4][4];
#pragma unroll
    for (int rr = 0; rr < 4; rr++)
#pragma unroll
        for (int c = 0; c < 4; c++) acc[rr][c] = bsv;
#pragma unroll 4
    for (int k = 0; k < 64; k++) {
        float4 w = reinterpret_cast<const float4*>(s_w1 + k * 64)[cgp];
#pragma unroll
        for (int rr = 0; rr < 4; rr++) {
            float y = s_y[(rl0 + rr) * 64 + k];
            acc[rr][0] = fmaf(y, w.x, acc[rr][0]);
            acc[rr][1] = fmaf(y, w.y, acc[rr][1]);
            acc[rr][2] = fmaf(y, w.z, acc[rr][2]);
            acc[rr][3] = fmaf(y, w.w, acc[rr][3]);
        }
    }
    __syncthreads();
#pragma unroll
    for (int rr = 0; rr < 4; rr++)
        reinterpret_cast<float4*>(s_y + (rl0 + rr) * 64)[cgp] =
            make_float4(fmaxf(acc[rr][0], 0.f), fmaxf(acc[rr][1], 0.f),
                        fmaxf(acc[rr][2], 0.f), fmaxf(acc[rr][3], 0.f));
    __syncthreads();

    float4 bz = *reinterpret_cast<const float4*>(b2 + c0);
#pragma unroll
    for (int rr = 0; rr < 4; rr++) { acc[rr][0] = bz.x; acc[rr][1] = bz.y; acc[rr][2] = bz.z; acc[rr][3] = bz.w; }
#pragma unroll 4
    for (int k = 0; k < 64; k++) {
        float4 w = reinterpret_cast<const float4*>(s_w2 + k * 64)[cgp];
#pragma unroll
        for (int rr = 0; rr < 4; rr++) {
            float y = s_y[(rl0 + rr) * 64 + k];
            acc[rr][0] = fmaf(y, w.x, acc[rr][0]);
            acc[rr][1] = fmaf(y, w.y, acc[rr][1]);
            acc[rr][2] = fmaf(y, w.z, acc[rr][2]);
            acc[rr][3] = fmaf(y, w.w, acc[rr][3]);
        }
    }
#pragma unroll
    for (int rr = 0; rr < 4; rr++)
#pragma unroll
        for (int c = 0; c < 4; c++) acc[rr][c] = fmaxf(acc[rr][c], 0.f);

#pragma unroll
    for (int rr = 0; rr < 4; rr++)
        *reinterpret_cast<float4*>(g_X2f + (size_t)(r0 + rl0 + rr) * NW + c0) =
            make_float4(acc[rr][0], acc[rr][1], acc[rr][2], acc[rr][3]);
#pragma unroll
    for (int c = 0; c < 4; c++) {
        __half2 h01 = __floats2half2_rn(acc[0][c], acc[1][c]);
        __half2 h23 = __floats2half2_rn(acc[2][c], acc[3][c]);
        __half2* base = reinterpret_cast<__half2*>(g_X2t + (size_t)(c0 + c) * N_NODES + r0 + rl0);
        base[0] = h01;
        base[1] = h23;
    }
}

// ---------------- last: combine + V2=relu(Y@wt2+bs2) + column partial sums ----------------
#define LAST_SMEM ((4096 * 2 + 64 + 1024) * 4)
__global__ __launch_bounds__(256) void last_kernel(const float* __restrict__ wt2,
                                                   const float* __restrict__ bs2) {
    extern __shared__ float sm[];
    float* s_w  = sm;
    float* s_y  = sm + 4096;
    float* s_zi = sm + 8192;
    float* s_part = sm + 8256;
    int tid = threadIdx.x;
    int r0 = blockIdx.x * 64;

    for (int i = tid; i < 4096; i += 256) s_w[i] = wt2[i];
    if (tid < 64) {
        float zs = 0.f;
#pragma unroll
        for (int p = 0; p < SPLITK; p++) zs += g_Zp[p][r0 + tid];
        s_zi[tid] = 1.0f / zs;
    }
    __syncthreads();

    const float4* X4 = reinterpret_cast<const float4*>(g_X2f + (size_t)r0 * NW);
    for (int i = tid; i < 1024; i += 256) {
        float4 v = reinterpret_cast<const float4*>(g_Yp[0] + (size_t)r0 * NW)[i];
#pragma unroll
        for (int p = 1; p < SPLITK; p++) {
            float4 t = reinterpret_cast<const float4*>(g_Yp[p] + (size_t)r0 * NW)[i];
            v.x += t.x; v.y += t.y; v.z += t.z; v.w += t.w;
        }
        float zi = s_zi[i >> 4];
        float4 xv = X4[i];
        reinterpret_cast<float4*>(s_y)[i] =
            make_float4(fmaf(v.x, zi, xv.x), fmaf(v.y, zi, xv.y),
                        fmaf(v.z, zi, xv.z), fmaf(v.w, zi, xv.w));
    }
    __syncthreads();

    int cgp = tid & 15, rg = tid >> 4;
    int c0 = cgp * 4, rl0 = rg * 4;
    float bv = bs2[0];
    float acc[4][4];
#pragma unroll
    for (int rr = 0; rr < 4; rr++)
#pragma unroll
        for (int c = 0; c < 4; c++) acc[rr][c] = bv;
#pragma unroll 4
    for (int k = 0; k < 64; k++) {
        float4 w = reinterpret_cast<const float4*>(s_w + k * 64)[cgp];
#pragma unroll
        for (int rr = 0; rr < 4; rr++) {
            float y = s_y[(rl0 + rr) * 64 + k];
            acc[rr][0] = fmaf(y, w.x, acc[rr][0]);
            acc[rr][1] = fmaf(y, w.y, acc[rr][1]);
            acc[rr][2] = fmaf(y, w.z, acc[rr][2]);
            acc[rr][3] = fmaf(y, w.w, acc[rr][3]);
        }
    }
#pragma unroll
    for (int c = 0; c < 4; c++) {
        float cs = fmaxf(acc[0][c], 0.f) + fmaxf(acc[1][c], 0.f) +
                   fmaxf(acc[2][c], 0.f) + fmaxf(acc[3][c], 0.f);
        s_part[rg * 64 + c0 + c] = cs;
    }
    __syncthreads();
    if (tid < 64) {
        float t = 0.f;
#pragma unroll
        for (int g = 0; g < 16; g++) t += s_part[g * 64 + tid];
        g_sp[blockIdx.x * NW + tid] = t;
    }
}

// ---------------- final: out = sigmoid(s@Wl + bl) ----------------
__global__ void final_kernel(const float* __restrict__ Wl, const float* __restrict__ bl,
                             float* __restrict__ out) {
    int n = threadIdx.x;  // 64 threads
    float s = 0.0f;
    for (int b = 0; b < 128; b++) s += g_sp[b * NW + n];
    float v = s * Wl[n];
    __shared__ float sh[64];
    sh[n] = v;
    __syncthreads();
    if (n < 32) {
        float t = sh[n] + sh[n + 32];
        for (int o = 16; o; o >>= 1) t += __shfl_down_sync(0xffffffffu, t, o);
        if (n == 0) out[0] = 1.0f / (1.0f + expf(-(t + bl[0])));
    }
}

// ---------------- launch ----------------
extern "C" void kernel_launch(void* const* d_in, const int* in_sizes, int n_in,
                              void* d_out, int out_size) {
    (void)in_sizes; (void)n_in; (void)out_size;
    const float* x     = (const float*)d_in[0];
    const float* alpha = (const float*)d_in[1];
    const float* W1    = (const float*)d_in[2];
    const float* b1    = (const float*)d_in[3];
    const float* wt1   = (const float*)d_in[4];
    const float* bs1   = (const float*)d_in[5];
    const float* W2    = (const float*)d_in[6];
    const float* b2    = (const float*)d_in[7];
    const float* wt2   = (const float*)d_in[8];
    const float* bs2   = (const float*)d_in[9];
    const float* Wl    = (const float*)d_in[10];
    const float* bl    = (const float*)d_in[11];
    float* out = (float*)d_out;

    cudaFuncSetAttribute(fused_gemm_kernel, cudaFuncAttributeMaxDynamicSharedMemorySize, BSMEM);
    cudaFuncSetAttribute(mid_kernel, cudaFuncAttributeMaxDynamicSharedMemorySize, MID_SMEM);
    cudaFuncSetAttribute(last_kernel, cudaFuncAttributeMaxDynamicSharedMemorySize, LAST_SMEM);

    prep_kernel<<<2048, 256>>>(x, W1, b1);

    fused_gemm_kernel<<<1024, 256, BSMEM>>>(0, alpha);
    mid_kernel<<<128, 256, MID_SMEM>>>(wt1, bs1, W2, b2);

    fused_gemm_kernel<<<1024, 256, BSMEM>>>(1, alpha);
    last_kernel<<<128, 256, LAST_SMEM>>>(wt2, bs2);

    final_kernel<<<1, 64>>>(Wl, bl, out);
}